// round 13
// baseline (speedup 1.0000x reference)
#include <cuda_runtime.h>
#include <cuda_fp16.h>
#include <cstdint>
#include <math.h>

#define Tn 256
#define Bn 256
#define Hn 512
#define BH (Bn*Hn)
#define G4 2048

// ---------------- device globals (scratch) ----------------
__device__ __align__(128) __half g_whh0[G4*Hn];
__device__ __align__(128) __half g_whh1[G4*Hn];
__device__ __align__(128) __half g_wih1[G4*Hn];
__device__ __align__(128) __half g_h0[(size_t)Tn*BH];
__device__ __align__(128) __half g_h1[(size_t)Tn*BH];
__device__ __align__(128) float g_xp[134217728];      // [t][bt][nt][tid(256)][32] fp32
// per-(layer,bt,mg,t) release counters, padded to 32B
__device__ __align__(128) unsigned g_cnt[16*257*8];

// ---------------- SMEM layout (bytes) ----------------
#define W0OFF 0
#define W1OFF 66560
#define ABASE 133120
#define WIH0OFF 202752
#define SMEMSZ 204800

// ---------------- PTX helpers ----------------
__device__ __forceinline__ uint32_t su32(const void* p){
    uint32_t a;
    asm("{ .reg .u64 t; cvta.to.shared.u64 t, %1; cvt.u32.u64 %0, t; }" : "=r"(a) : "l"(p));
    return a;
}
__device__ __forceinline__ void ldmx4(uint32_t* r, uint32_t a){
    asm volatile("ldmatrix.sync.aligned.m8n8.x4.shared.b16 {%0,%1,%2,%3}, [%4];"
        : "=r"(r[0]), "=r"(r[1]), "=r"(r[2]), "=r"(r[3]) : "r"(a));
}
__device__ __forceinline__ void mma_f16(float* c, const uint32_t* a, uint32_t b0, uint32_t b1){
    asm("mma.sync.aligned.m16n8k16.row.col.f32.f16.f16.f32 "
        "{%0,%1,%2,%3}, {%4,%5,%6,%7}, {%8,%9}, {%0,%1,%2,%3};"
        : "+f"(c[0]), "+f"(c[1]), "+f"(c[2]), "+f"(c[3])
        : "r"(a[0]), "r"(a[1]), "r"(a[2]), "r"(a[3]), "r"(b0), "r"(b1));
}
__device__ __forceinline__ void cpa16(uint32_t dst, const void* src){
    asm volatile("cp.async.cg.shared.global [%0], [%1], 16;" :: "r"(dst), "l"(src));
}
#define CP_COMMIT asm volatile("cp.async.commit_group;" ::: "memory")
#define CP_WAIT0  asm volatile("cp.async.wait_group 0;" ::: "memory")
#define CP_WAIT1  asm volatile("cp.async.wait_group 1;" ::: "memory")
#define PAIRBAR(mg) asm volatile("bar.sync %0, 64;" :: "r"((mg)+1) : "memory")

__device__ __forceinline__ uint32_t packh2(float a, float b){
    __half2 v = __floats2half2_rn(a, b);
    return *(uint32_t*)&v;
}
__device__ __forceinline__ float fsig(float x){
    return __fdividef(1.f, 1.f + __expf(-x));
}
__device__ __forceinline__ float ftanh(float x){
    return 1.f - __fdividef(2.f, __expf(2.f*x) + 1.f);
}

// ---------------- per-warp counter sync ----------------
__device__ __forceinline__ unsigned* cnt_ptr(int layer, int bt, int mg, int t){
    return &g_cnt[(size_t)(((layer*2 + bt)*4 + mg)*257 + t)*8];
}
__device__ __forceinline__ void warp_wait(unsigned* p, unsigned tgt, int lane){
    if (lane == 0){
        volatile unsigned* v = p;
        while (*v < tgt) {}
        __threadfence();
    }
    __syncwarp();
}
__device__ __forceinline__ void warp_publish(unsigned* p, int lane){
    __threadfence();
    __syncwarp();
    if (lane == 0) atomicAdd(p, 1u);
}

// ---------------- prologue ----------------
__global__ void conv_all_kernel(const float* __restrict__ whh0,
                                const float* __restrict__ whh1,
                                const float* __restrict__ wih1)
{
    int i = blockIdx.x * blockDim.x + threadIdx.x;
    if (i < 16*257*8) g_cnt[i] = 0u;
    if (i >= G4*Hn) return;
    g_whh0[i] = __float2half_rn(whh0[i]);
    g_whh1[i] = __float2half_rn(whh1[i]);
    g_wih1[i] = __float2half_rn(wih1[i]);
}

// ---------------- staging ----------------
__device__ __forceinline__ void stage_half(const __half* __restrict__ src,
                                           int kc, uint32_t buf, int mg, int nh, int lane)
{
    #pragma unroll
    for (int it = 0; it < 8; ++it){
        int idx = it*32 + lane;
        int r   = idx >> 4;
        int s   = idx & 15;
        cpa16(buf + (uint32_t)((nh*16 + r)*272 + s*16),
              src + (size_t)(mg*32 + nh*16 + r) * Hn + kc*128 + s*8);
    }
}

__device__ __forceinline__ void stage_W(const __half* __restrict__ src,
                                        char* smem, int woff, int u0, int tid)
{
    for (int it = 0; it < 16; ++it){
        int idx = tid + it*256;
        int row = idx >> 6;
        int kk  = (idx & 63) << 3;
        int j = ((row >> 3) & 3) * Hn + u0 + (row & 7) + (row >> 5) * 8;
        uint4 v = *(const uint4*)(src + (size_t)j * Hn + kk);
        *(uint4*)(smem + woff + row*1040 + kk*2) = v;
    }
}

// ---------------- fragment pipelines ----------------
struct Fr2 { uint32_t a[8], wr[8], wx[8]; };
struct Fr1 { uint32_t a[8], wr[8]; };

__device__ __forceinline__ void load2(Fr2& f, uint32_t aB, uint32_t wrB, uint32_t wxB, int k16){
    ldmx4(f.a,     aB + k16*32);
    ldmx4(f.a + 4, aB + 4352 + k16*32);
    ldmx4(f.wr,     wrB + k16*32);
    ldmx4(f.wr + 4, wrB + 16640 + k16*32);
    ldmx4(f.wx,     wxB + k16*32);
    ldmx4(f.wx + 4, wxB + 16640 + k16*32);
}
__device__ __forceinline__ void load1(Fr1& f, uint32_t aB, uint32_t wrB, int k16){
    ldmx4(f.a,     aB + k16*32);
    ldmx4(f.a + 4, aB + 4352 + k16*32);
    ldmx4(f.wr,     wrB + k16*32);
    ldmx4(f.wr + 4, wrB + 16640 + k16*32);
}

__device__ __forceinline__ void chunk2(uint32_t aB, uint32_t wrB, uint32_t wxB,
                                       float* accR, float* accX)
{
    Fr2 f[2];
    load2(f[0], aB, wrB, wxB, 0);
    #pragma unroll
    for (int k16 = 0; k16 < 8; ++k16){
        if (k16 < 7) load2(f[(k16+1)&1], aB, wrB, wxB, k16+1);
        const Fr2& fc = f[k16&1];
        #pragma unroll
        for (int mh = 0; mh < 2; ++mh)
            #pragma unroll
            for (int g = 0; g < 4; ++g)
                mma_f16(accR + (mh*4+g)*4, fc.a + mh*4, fc.wr[g*2], fc.wr[g*2+1]);
        #pragma unroll
        for (int mh = 0; mh < 2; ++mh)
            #pragma unroll
            for (int g = 0; g < 4; ++g)
                mma_f16(accX + (mh*4+g)*4, fc.a + mh*4, fc.wx[g*2], fc.wx[g*2+1]);
    }
}
__device__ __forceinline__ void chunk1(uint32_t aB, uint32_t wrB, float* accR)
{
    Fr1 f[2];
    load1(f[0], aB, wrB, 0);
    #pragma unroll
    for (int k16 = 0; k16 < 8; ++k16){
        if (k16 < 7) load1(f[(k16+1)&1], aB, wrB, k16+1);
        const Fr1& fc = f[k16&1];
        #pragma unroll
        for (int mh = 0; mh < 2; ++mh)
            #pragma unroll
            for (int g = 0; g < 4; ++g)
                mma_f16(accR + (mh*4+g)*4, fc.a + mh*4, fc.wr[g*2], fc.wr[g*2+1]);
    }
}

// chunk-range pair-synchronized GEMM (role-0 and t=0 path)
template<int XPC>
__device__ __forceinline__ void gemm_loop(const __half* __restrict__ src, uint32_t sb,
    uint32_t aoff, uint32_t wboff, int wrOFF, float* accR, float* accX,
    int c0, int c1, int mg, int nh, int lane)
{
    const uint32_t buf0 = sb + ABASE + (uint32_t)mg*17408u;
    const uint32_t bufs[2] = {buf0, buf0 + 8704u};
    stage_half(src, c0, bufs[c0 & 1], mg, nh, lane); CP_COMMIT;
    if (c0 + 1 < c1){ stage_half(src, c0+1, bufs[(c0+1) & 1], mg, nh, lane); CP_COMMIT; }
    #pragma unroll 1
    for (int c = c0; c < c1; ++c){
        if (c + 1 < c1) { CP_WAIT1; } else { CP_WAIT0; }
        PAIRBAR(mg);
        uint32_t aB = bufs[c & 1] + aoff;
        if (c < XPC)
            chunk2(aB, sb + wrOFF + wboff + c*256, sb + W1OFF + wboff + c*256, accR, accX);
        else
            chunk1(aB, sb + wrOFF + wboff + c*256, accR);
        PAIRBAR(mg);
        if (c + 2 < c1){ stage_half(src, c+2, bufs[c & 1], mg, nh, lane); CP_COMMIT; }
    }
}

// ---------------- fused two-layer pipelined kernel ----------------
__global__ void __launch_bounds__(256, 1) lstm_fused(
    const float* __restrict__ x_time, const float* __restrict__ w_ih0,
    const float* __restrict__ bias0, const float* __restrict__ bias1)
{
    extern __shared__ __align__(128) char smem[];
    const int tid  = threadIdx.x;
    const int lane = tid & 31;
    const int wid  = tid >> 5;
    const int mg   = wid >> 1;
    const int nh   = wid & 1;
    const int role = blockIdx.x >> 6;
    const int lidx = blockIdx.x & 63;
    const int bt   = lidx >> 5;
    const int nt   = lidx & 31;
    const int b0   = bt * 128;
    const int u0   = nt * 16;
    const uint32_t sb = su32(smem);

    const uint32_t aoff  = (uint32_t)((lane & 15) * 272 + (lane >> 4) * 16);
    const uint32_t wboff = (uint32_t)((nh*32 + (lane & 7) + ((lane >> 4) & 1) * 8) * 1040
                                      + ((lane >> 3) & 1) * 16);
    const int q2    = 2 * (lane & 3);
    const int rb0   = mg*32 + (lane >> 2);
    const int ubase = u0 + nh*8 + q2;

    if (role == 0){
        // ================= layer 0 + xp (K 0..255) producer =================
        stage_W(g_whh0, smem, W0OFF, u0, tid);
        stage_W(g_wih1, smem, W1OFF, u0, tid);
        float* s_wih0 = (float*)(smem + WIH0OFF);
        if (tid < 64){
            int j = ((tid >> 3) & 3) * Hn + u0 + (tid & 7) + (tid >> 5) * 8;
            #pragma unroll
            for (int q = 0; q < 5; ++q) s_wih0[tid*5 + q] = w_ih0[(size_t)j*5 + q];
        }
        float breg[4][2], bx[4][2];
        #pragma unroll
        for (int g = 0; g < 4; ++g){
            breg[g][0] = bias0[g*Hn + ubase];
            breg[g][1] = bias0[g*Hn + ubase + 1];
            bx[g][0]   = bias1[g*Hn + ubase];
            bx[g][1]   = bias1[g*Hn + ubase + 1];
        }
        __syncthreads();

        float c[8];
        #pragma unroll
        for (int i = 0; i < 8; ++i) c[i] = 0.f;

        for (int t = 0; t <= Tn; ++t){
            float xr[4][5];
            if (t < Tn){
                #pragma unroll
                for (int mh = 0; mh < 2; ++mh)
                    #pragma unroll
                    for (int rs = 0; rs < 2; ++rs){
                        const float* p = x_time
                            + ((size_t)(b0 + rb0 + mh*16 + rs*8) * Tn + t) * 5;
                        #pragma unroll
                        for (int q = 0; q < 5; ++q) xr[mh*2+rs][q] = p[q];
                    }
            }

            float accR[32], accX[32];
            #pragma unroll
            for (int i = 0; i < 32; ++i){ accR[i] = 0.f; accX[i] = 0.f; }

            if (t > 0){
                warp_wait(cnt_ptr(0, bt, mg, t-1), 64u, lane);
                gemm_loop<2>(g_h0 + (size_t)(t-1)*BH + (size_t)b0*Hn, sb, aoff, wboff,
                             W0OFF, accR, accX, 0, 4, mg, nh, lane);
            }

            if (t < Tn){
                #pragma unroll
                for (int mh = 0; mh < 2; ++mh)
                    #pragma unroll
                    for (int rs = 0; rs < 2; ++rs)
                        #pragma unroll
                        for (int g = 0; g < 4; ++g)
                            #pragma unroll
                            for (int j = 0; j < 2; ++j){
                                const float* wr = s_wih0 + (nh*32 + g*8 + q2 + j)*5;
                                float d = breg[g][j];
                                #pragma unroll
                                for (int q = 0; q < 5; ++q) d += xr[mh*2+rs][q]*wr[q];
                                accR[(mh*4+g)*4 + rs*2 + j] += d;
                            }
                #pragma unroll
                for (int mh = 0; mh < 2; ++mh)
                    #pragma unroll
                    for (int rs = 0; rs < 2; ++rs){
                        int row = rb0 + mh*16 + rs*8;
                        float hv[2];
                        #pragma unroll
                        for (int j = 0; j < 2; ++j){
                            float ai = accR[(mh*4+0)*4 + rs*2 + j];
                            float af = accR[(mh*4+1)*4 + rs*2 + j];
                            float ag = accR[(mh*4+2)*4 + rs*2 + j];
                            float ao = accR[(mh*4+3)*4 + rs*2 + j];
                            int ci = mh*4 + rs*2 + j;
                            c[ci] = fsig(af) * c[ci] + fsig(ai) * ftanh(ag);
                            hv[j] = fsig(ao) * ftanh(c[ci]);
                        }
                        size_t ob = (size_t)t*BH + (size_t)(b0+row)*Hn + ubase;
                        *(uint32_t*)(g_h0 + ob) = packh2(hv[0], hv[1]);
                    }
            }

            if (t > 0){
                float* xp = g_xp + ((((size_t)(t-1)*2 + bt)*32 + nt)*256 + tid)*32;
                #pragma unroll
                for (int mh = 0; mh < 2; ++mh)
                    #pragma unroll
                    for (int g = 0; g < 4; ++g){
                        int i = mh*4 + g;
                        float4 v;
                        v.x = accX[i*4+0] + bx[g][0];
                        v.y = accX[i*4+1] + bx[g][1];
                        v.z = accX[i*4+2] + bx[g][0];
                        v.w = accX[i*4+3] + bx[g][1];
                        *(float4*)(xp + i*4) = v;
                    }
            }

            warp_publish(cnt_ptr(0, bt, mg, t), lane);
        }
    } else {
        // ================= layer 1 + xp (K 256..511), fused 6-chunk pipeline ========
        stage_W(g_whh1, smem, W0OFF, u0, tid);
        stage_W(g_wih1, smem, W1OFF, u0, tid);
        __syncthreads();

        const uint32_t buf0 = sb + ABASE + (uint32_t)mg*17408u;
        const uint32_t bufs[2] = {buf0, buf0 + 8704u};

        float c[8];
        #pragma unroll
        for (int i = 0; i < 8; ++i) c[i] = 0.f;

        for (int t = 0; t < Tn; ++t){
            const __half* h0src = g_h0 + (size_t)t*BH + (size_t)b0*Hn;

            float accR[32];
            #pragma unroll
            for (int i = 0; i < 32; ++i) accR[i] = 0.f;

            if (t > 0){
                const __half* h1src = g_h1 + (size_t)(t-1)*BH + (size_t)b0*Hn;
                // OLD dependency first: own-layer peers (lag 1)
                warp_wait(cnt_ptr(1, bt, mg, t-1), 64u, lane);
                stage_half(h1src, 0, bufs[0], mg, nh, lane); CP_COMMIT;
                stage_half(h1src, 1, bufs[1], mg, nh, lane); CP_COMMIT;
                // seq: rec c0..c3 (h1,W0OFF), xp c2,c3 (h0,W1OFF)
                #pragma unroll 1
                for (int i = 0; i < 6; ++i){
                    if (i < 5) { CP_WAIT1; } else { CP_WAIT0; }
                    PAIRBAR(mg);
                    int ci   = (i < 4) ? i : (i - 2);
                    int woff = (i < 4) ? W0OFF : W1OFF;
                    chunk1(bufs[i & 1] + aoff, sb + woff + wboff + ci*256, accR);
                    PAIRBAR(mg);
                    if (i + 2 < 6){
                        // FRESH dependency just-in-time, hidden behind rec chunks
                        if (i == 2) warp_wait(cnt_ptr(0, bt, mg, t+1), 64u, lane);
                        int cj = (i + 2 < 4) ? (i + 2) : i;
                        const __half* s2 = (i + 2 < 4) ? h1src : h0src;
                        stage_half(s2, cj, bufs[i & 1], mg, nh, lane); CP_COMMIT;
                    }
                }
            } else {
                warp_wait(cnt_ptr(0, bt, mg, 1), 64u, lane);
                gemm_loop<0>(h0src, sb, aoff, wboff, W1OFF, accR, (float*)0,
                             2, 4, mg, nh, lane);
            }

            // xp partial (K 0..255 + bias1): cnt0[t+1] already satisfied above
            {
                const float* xps = g_xp + ((((size_t)t*2 + bt)*32 + nt)*256 + tid)*32;
                #pragma unroll
                for (int i = 0; i < 8; ++i){
                    float4 v = *(const float4*)(xps + i*4);
                    accR[i*4+0] += v.x; accR[i*4+1] += v.y;
                    accR[i*4+2] += v.z; accR[i*4+3] += v.w;
                }
            }

            #pragma unroll
            for (int mh = 0; mh < 2; ++mh)
                #pragma unroll
                for (int rs = 0; rs < 2; ++rs){
                    int row = rb0 + mh*16 + rs*8;
                    float hv[2];
                    #pragma unroll
                    for (int j = 0; j < 2; ++j){
                        float ai = accR[(mh*4+0)*4 + rs*2 + j];
                        float af = accR[(mh*4+1)*4 + rs*2 + j];
                        float ag = accR[(mh*4+2)*4 + rs*2 + j];
                        float ao = accR[(mh*4+3)*4 + rs*2 + j];
                        int ci = mh*4 + rs*2 + j;
                        c[ci] = fsig(af) * c[ci] + fsig(ai) * ftanh(ag);
                        hv[j] = fsig(ao) * ftanh(c[ci]);
                    }
                    size_t ob = (size_t)t*BH + (size_t)(b0+row)*Hn + ubase;
                    *(uint32_t*)(g_h1 + ob) = packh2(hv[0], hv[1]);
                }

            warp_publish(cnt_ptr(1, bt, mg, t), lane);
        }
    }
}

// ---------------- heads ----------------
__global__ void __launch_bounds__(256) heads_kernel(
    const float* __restrict__ x_stat,
    const float* __restrict__ fc1_w, const float* __restrict__ fc1_b,
    const float* __restrict__ fc2_w, const float* __restrict__ fc2_b,
    const float* __restrict__ fc3_w, const float* __restrict__ fc3_b,
    float* __restrict__ out)
{
    const int b = blockIdx.x;
    const int tid = threadIdx.x;

    float p0 = 0.f, p1 = 0.f;
    for (int idx = tid; idx < Tn*Hn; idx += 256){
        int t = idx >> 9;
        int u = idx & 511;
        float hv = __half2float(g_h1[(size_t)t * BH + (size_t)b * Hn + u]);
        p0 += hv * fc1_w[idx];
        p1 += hv * fc1_w[Tn*Hn + idx];
    }
    __shared__ float s0[256], s1[256];
    s0[tid] = p0; s1[tid] = p1;
    __syncthreads();
    for (int s = 128; s > 0; s >>= 1){
        if (tid < s){ s0[tid] += s0[tid+s]; s1[tid] += s1[tid+s]; }
        __syncthreads();
    }
    if (tid == 0){
        float tp0 = s0[0] + fc1_b[0];
        float tp1 = s1[0] + fc1_b[1];
        float xs0 = x_stat[b*3+0], xs1 = x_stat[b*3+1], xs2 = x_stat[b*3+2];
        float sp0 = fc2_b[0] + xs0*fc2_w[0] + xs1*fc2_w[1] + xs2*fc2_w[2];
        float sp1 = fc2_b[1] + xs0*fc2_w[3] + xs1*fc2_w[4] + xs2*fc2_w[5];
        out[b*2+0] = fc3_b[0] + fc3_w[0]*sp0 + fc3_w[1]*sp1 + fc3_w[2]*tp0 + fc3_w[3]*tp1;
        out[b*2+1] = fc3_b[1] + fc3_w[4]*sp0 + fc3_w[5]*sp1 + fc3_w[6]*tp0 + fc3_w[7]*tp1;
    }
}

extern "C" void kernel_launch(void* const* d_in, const int* in_sizes, int n_in,
                              void* d_out, int out_size)
{
    const float* x_time = (const float*)d_in[0];
    const float* x_stat = (const float*)d_in[1];
    const float* w_ih0  = (const float*)d_in[2];
    const float* w_hh0  = (const float*)d_in[3];
    const float* b0     = (const float*)d_in[4];
    const float* w_ih1  = (const float*)d_in[5];
    const float* w_hh1  = (const float*)d_in[6];
    const float* b1     = (const float*)d_in[7];
    const float* fc1_w  = (const float*)d_in[8];
    const float* fc1_b  = (const float*)d_in[9];
    const float* fc2_w  = (const float*)d_in[10];
    const float* fc2_b  = (const float*)d_in[11];
    const float* fc3_w  = (const float*)d_in[12];
    const float* fc3_b  = (const float*)d_in[13];
    float* out = (float*)d_out;

    cudaFuncSetAttribute(lstm_fused, cudaFuncAttributeMaxDynamicSharedMemorySize, SMEMSZ);

    conv_all_kernel<<<(G4*Hn + 255)/256, 256>>>(w_hh0, w_hh1, w_ih1);
    lstm_fused<<<128, 256, SMEMSZ>>>(x_time, w_ih0, b0, b1);
    heads_kernel<<<Bn, 256>>>(x_stat, fc1_w, fc1_b, fc2_w, fc2_b, fc3_w, fc3_b, out);
}

// round 14
// speedup vs baseline: 1.0593x; 1.0593x over previous
#include <cuda_runtime.h>
#include <cuda_fp16.h>
#include <cstdint>
#include <math.h>

#define Tn 256
#define Bn 256
#define Hn 512
#define BH (Bn*Hn)
#define G4 2048

// ---------------- device globals (scratch) ----------------
__device__ __align__(128) __half g_whh0[G4*Hn];
__device__ __align__(128) __half g_whh1[G4*Hn];
__device__ __align__(128) __half g_wih1[G4*Hn];
__device__ __align__(128) __half g_h0[(size_t)Tn*BH];
__device__ __align__(128) __half g_h1[(size_t)Tn*BH];
__device__ __align__(128) float g_xp[134217728];      // [t][bt][nt][tid(256)][32] fp32
// counters: key (k, bt, mg, t); k=0 cnt0h, k=1 cnt1, k=2 cnt0x
__device__ __align__(128) unsigned g_cnt[16*257*8];

// ---------------- SMEM layout (bytes) ----------------
#define W0OFF 0
#define W1OFF 66560
#define ABASE 133120
#define WIH0OFF 202752
#define SMEMSZ 204800

// ---------------- PTX helpers ----------------
__device__ __forceinline__ uint32_t su32(const void* p){
    uint32_t a;
    asm("{ .reg .u64 t; cvta.to.shared.u64 t, %1; cvt.u32.u64 %0, t; }" : "=r"(a) : "l"(p));
    return a;
}
__device__ __forceinline__ void ldmx4(uint32_t* r, uint32_t a){
    asm volatile("ldmatrix.sync.aligned.m8n8.x4.shared.b16 {%0,%1,%2,%3}, [%4];"
        : "=r"(r[0]), "=r"(r[1]), "=r"(r[2]), "=r"(r[3]) : "r"(a));
}
__device__ __forceinline__ void mma_f16(float* c, const uint32_t* a, uint32_t b0, uint32_t b1){
    asm("mma.sync.aligned.m16n8k16.row.col.f32.f16.f16.f32 "
        "{%0,%1,%2,%3}, {%4,%5,%6,%7}, {%8,%9}, {%0,%1,%2,%3};"
        : "+f"(c[0]), "+f"(c[1]), "+f"(c[2]), "+f"(c[3])
        : "r"(a[0]), "r"(a[1]), "r"(a[2]), "r"(a[3]), "r"(b0), "r"(b1));
}
__device__ __forceinline__ void cpa16(uint32_t dst, const void* src){
    asm volatile("cp.async.cg.shared.global [%0], [%1], 16;" :: "r"(dst), "l"(src));
}
#define CP_COMMIT asm volatile("cp.async.commit_group;" ::: "memory")
#define CP_WAIT0  asm volatile("cp.async.wait_group 0;" ::: "memory")
#define CP_WAIT1  asm volatile("cp.async.wait_group 1;" ::: "memory")
#define PAIRBAR(mg) asm volatile("bar.sync %0, 64;" :: "r"((mg)+1) : "memory")

__device__ __forceinline__ uint32_t packh2(float a, float b){
    __half2 v = __floats2half2_rn(a, b);
    return *(uint32_t*)&v;
}
__device__ __forceinline__ float fsig(float x){
    return __fdividef(1.f, 1.f + __expf(-x));
}
__device__ __forceinline__ float ftanh(float x){
    return 1.f - __fdividef(2.f, __expf(2.f*x) + 1.f);
}

// ---------------- per-warp counter sync ----------------
__device__ __forceinline__ unsigned* cnt_ptr(int k, int bt, int mg, int t){
    return &g_cnt[(size_t)(((k*2 + bt)*4 + mg)*257 + t)*8];
}
__device__ __forceinline__ void warp_wait(unsigned* p, unsigned tgt, int lane){
    if (lane == 0){
        volatile unsigned* v = p;
        while (*v < tgt) {}
        __threadfence();
    }
    __syncwarp();
}
__device__ __forceinline__ void warp_publish(unsigned* p, int lane){
    __threadfence();
    __syncwarp();
    if (lane == 0) atomicAdd(p, 1u);
}

// ---------------- prologue ----------------
__global__ void conv_all_kernel(const float* __restrict__ whh0,
                                const float* __restrict__ whh1,
                                const float* __restrict__ wih1)
{
    int i = blockIdx.x * blockDim.x + threadIdx.x;
    if (i < 16*257*8) g_cnt[i] = 0u;
    if (i >= G4*Hn) return;
    g_whh0[i] = __float2half_rn(whh0[i]);
    g_whh1[i] = __float2half_rn(whh1[i]);
    g_wih1[i] = __float2half_rn(wih1[i]);
}

// ---------------- staging ----------------
__device__ __forceinline__ void stage_half(const __half* __restrict__ src,
                                           int kc, uint32_t buf, int mg, int nh, int lane)
{
    #pragma unroll
    for (int it = 0; it < 8; ++it){
        int idx = it*32 + lane;
        int r   = idx >> 4;
        int s   = idx & 15;
        cpa16(buf + (uint32_t)((nh*16 + r)*272 + s*16),
              src + (size_t)(mg*32 + nh*16 + r) * Hn + kc*128 + s*8);
    }
}

__device__ __forceinline__ void stage_W(const __half* __restrict__ src,
                                        char* smem, int woff, int u0, int tid)
{
    for (int it = 0; it < 16; ++it){
        int idx = tid + it*256;
        int row = idx >> 6;
        int kk  = (idx & 63) << 3;
        int j = ((row >> 3) & 3) * Hn + u0 + (row & 7) + (row >> 5) * 8;
        uint4 v = *(const uint4*)(src + (size_t)j * Hn + kk);
        *(uint4*)(smem + woff + row*1040 + kk*2) = v;
    }
}

// ---------------- fragment pipeline (warp tile 32x32) ----------------
struct Fr1 { uint32_t a[8], wr[8]; };

__device__ __forceinline__ void load1(Fr1& f, uint32_t aB, uint32_t wrB, int k16){
    ldmx4(f.a,     aB + k16*32);
    ldmx4(f.a + 4, aB + 4352 + k16*32);
    ldmx4(f.wr,     wrB + k16*32);
    ldmx4(f.wr + 4, wrB + 16640 + k16*32);
}
__device__ __forceinline__ void chunk1(uint32_t aB, uint32_t wrB, float* accR)
{
    Fr1 f[2];
    load1(f[0], aB, wrB, 0);
    #pragma unroll
    for (int k16 = 0; k16 < 8; ++k16){
        if (k16 < 7) load1(f[(k16+1)&1], aB, wrB, k16+1);
        const Fr1& fc = f[k16&1];
        #pragma unroll
        for (int mh = 0; mh < 2; ++mh)
            #pragma unroll
            for (int g = 0; g < 4; ++g)
                mma_f16(accR + (mh*4+g)*4, fc.a + mh*4, fc.wr[g*2], fc.wr[g*2+1]);
    }
}

// chunk-range pair-synchronized rec-only GEMM
__device__ __forceinline__ void gemm_loop(const __half* __restrict__ src, uint32_t sb,
    uint32_t aoff, uint32_t wboff, int wrOFF, float* accR,
    int c0, int c1, int mg, int nh, int lane)
{
    const uint32_t buf0 = sb + ABASE + (uint32_t)mg*17408u;
    const uint32_t bufs[2] = {buf0, buf0 + 8704u};
    stage_half(src, c0, bufs[c0 & 1], mg, nh, lane); CP_COMMIT;
    if (c0 + 1 < c1){ stage_half(src, c0+1, bufs[(c0+1) & 1], mg, nh, lane); CP_COMMIT; }
    #pragma unroll 1
    for (int c = c0; c < c1; ++c){
        if (c + 1 < c1) { CP_WAIT1; } else { CP_WAIT0; }
        PAIRBAR(mg);
        chunk1(bufs[c & 1] + aoff, sb + wrOFF + wboff + c*256, accR);
        PAIRBAR(mg);
        if (c + 2 < c1){ stage_half(src, c+2, bufs[c & 1], mg, nh, lane); CP_COMMIT; }
    }
}

// ---------------- fused two-layer pipelined kernel ----------------
// 128 CTAs: role 0 = layer0 rec (critical path) + xp K-chunks 2..3 (off-path);
//           role 1 = layer1 rec + xp K-chunks 0..1.
// Per role: 2 bt (128 b) x 32 nt (16 u). 8 warps: mg = wid>>1 (m32), nh = wid&1 (n32).
__global__ void __launch_bounds__(256, 1) lstm_fused(
    const float* __restrict__ x_time, const float* __restrict__ w_ih0,
    const float* __restrict__ bias0, const float* __restrict__ bias1)
{
    extern __shared__ __align__(128) char smem[];
    const int tid  = threadIdx.x;
    const int lane = tid & 31;
    const int wid  = tid >> 5;
    const int mg   = wid >> 1;
    const int nh   = wid & 1;
    const int role = blockIdx.x >> 6;
    const int lidx = blockIdx.x & 63;
    const int bt   = lidx >> 5;
    const int nt   = lidx & 31;
    const int b0   = bt * 128;
    const int u0   = nt * 16;
    const uint32_t sb = su32(smem);

    const uint32_t aoff  = (uint32_t)((lane & 15) * 272 + (lane >> 4) * 16);
    const uint32_t wboff = (uint32_t)((nh*32 + (lane & 7) + ((lane >> 4) & 1) * 8) * 1040
                                      + ((lane >> 3) & 1) * 16);
    const int q2    = 2 * (lane & 3);
    const int rb0   = mg*32 + (lane >> 2);
    const int ubase = u0 + nh*8 + q2;

    const uint32_t buf0 = sb + ABASE + (uint32_t)mg*17408u;
    const uint32_t bufs[2] = {buf0, buf0 + 8704u};

    if (role == 0){
        // ================= layer 0 (critical) + xp K 256..511 (off-path) =========
        stage_W(g_whh0, smem, W0OFF, u0, tid);
        stage_W(g_wih1, smem, W1OFF, u0, tid);
        float* s_wih0 = (float*)(smem + WIH0OFF);
        if (tid < 64){
            int j = ((tid >> 3) & 3) * Hn + u0 + (tid & 7) + (tid >> 5) * 8;
            #pragma unroll
            for (int q = 0; q < 5; ++q) s_wih0[tid*5 + q] = w_ih0[(size_t)j*5 + q];
        }
        float breg[4][2], bx[4][2];
        #pragma unroll
        for (int g = 0; g < 4; ++g){
            breg[g][0] = bias0[g*Hn + ubase];
            breg[g][1] = bias0[g*Hn + ubase + 1];
            bx[g][0]   = bias1[g*Hn + ubase];
            bx[g][1]   = bias1[g*Hn + ubase + 1];
        }
        __syncthreads();

        float c[8];
        #pragma unroll
        for (int i = 0; i < 8; ++i) c[i] = 0.f;

        for (int t = 0; t <= Tn; ++t){
            float xr[4][5];
            if (t < Tn){
                #pragma unroll
                for (int mh = 0; mh < 2; ++mh)
                    #pragma unroll
                    for (int rs = 0; rs < 2; ++rs){
                        const float* p = x_time
                            + ((size_t)(b0 + rb0 + mh*16 + rs*8) * Tn + t) * 5;
                        #pragma unroll
                        for (int q = 0; q < 5; ++q) xr[mh*2+rs][q] = p[q];
                    }
            }

            float accR[32];
            #pragma unroll
            for (int i = 0; i < 32; ++i) accR[i] = 0.f;

            if (t > 0){
                warp_wait(cnt_ptr(0, bt, mg, t-1), 64u, lane);
                gemm_loop(g_h0 + (size_t)(t-1)*BH + (size_t)b0*Hn, sb, aoff, wboff,
                          W0OFF, accR, 0, 4, mg, nh, lane);
            }

            if (t < Tn){
                #pragma unroll
                for (int mh = 0; mh < 2; ++mh)
                    #pragma unroll
                    for (int rs = 0; rs < 2; ++rs)
                        #pragma unroll
                        for (int g = 0; g < 4; ++g)
                            #pragma unroll
                            for (int j = 0; j < 2; ++j){
                                const float* wr = s_wih0 + (nh*32 + g*8 + q2 + j)*5;
                                float d = breg[g][j];
                                #pragma unroll
                                for (int q = 0; q < 5; ++q) d += xr[mh*2+rs][q]*wr[q];
                                accR[(mh*4+g)*4 + rs*2 + j] += d;
                            }
                #pragma unroll
                for (int mh = 0; mh < 2; ++mh)
                    #pragma unroll
                    for (int rs = 0; rs < 2; ++rs){
                        int row = rb0 + mh*16 + rs*8;
                        float hv[2];
                        #pragma unroll
                        for (int j = 0; j < 2; ++j){
                            float ai = accR[(mh*4+0)*4 + rs*2 + j];
                            float af = accR[(mh*4+1)*4 + rs*2 + j];
                            float ag = accR[(mh*4+2)*4 + rs*2 + j];
                            float ao = accR[(mh*4+3)*4 + rs*2 + j];
                            int ci = mh*4 + rs*2 + j;
                            c[ci] = fsig(af) * c[ci] + fsig(ai) * ftanh(ag);
                            hv[j] = fsig(ao) * ftanh(c[ci]);
                        }
                        size_t ob = (size_t)t*BH + (size_t)(b0+row)*Hn + ubase;
                        *(uint32_t*)(g_h0 + ob) = packh2(hv[0], hv[1]);
                    }
            }

            // publish h0_t FIRST — unblocks peers & L1 before xp work
            warp_publish(cnt_ptr(0, bt, mg, t), lane);

            if (t > 0){
                // xp_{t-1} K-chunks 2,3 from STILL-RESIDENT bufs (no restaging)
                float accX[32];
                #pragma unroll
                for (int i = 0; i < 32; ++i) accX[i] = 0.f;
                chunk1(bufs[0] + aoff, sb + W1OFF + wboff + 2*256, accX);
                chunk1(bufs[1] + aoff, sb + W1OFF + wboff + 3*256, accX);
                float* xp = g_xp + ((((size_t)(t-1)*2 + bt)*32 + nt)*256 + tid)*32;
                #pragma unroll
                for (int mh = 0; mh < 2; ++mh)
                    #pragma unroll
                    for (int g = 0; g < 4; ++g){
                        int i = mh*4 + g;
                        float4 v;
                        v.x = accX[i*4+0] + bx[g][0];
                        v.y = accX[i*4+1] + bx[g][1];
                        v.z = accX[i*4+2] + bx[g][0];
                        v.w = accX[i*4+3] + bx[g][1];
                        *(float4*)(xp + i*4) = v;
                    }
                warp_publish(cnt_ptr(2, bt, mg, t-1), lane);
                PAIRBAR(mg);   // sibling done reading bufs before next step restages
            }
        }
    } else {
        // ================= layer 1 + xp K 0..255 =================
        stage_W(g_whh1, smem, W0OFF, u0, tid);
        stage_W(g_wih1, smem, W1OFF, u0, tid);
        __syncthreads();

        float c[8];
        #pragma unroll
        for (int i = 0; i < 8; ++i) c[i] = 0.f;

        for (int t = 0; t < Tn; ++t){
            float accR[32];
            #pragma unroll
            for (int i = 0; i < 32; ++i) accR[i] = 0.f;

            // xp K 0..255: stage h0_t chunks 0,1 vs wih1 (cnt0h[t] ~1 period old)
            warp_wait(cnt_ptr(0, bt, mg, t), 64u, lane);
            gemm_loop(g_h0 + (size_t)t*BH + (size_t)b0*Hn, sb, aoff, wboff,
                      W1OFF, accR, 0, 2, mg, nh, lane);

            if (t > 0){
                warp_wait(cnt_ptr(1, bt, mg, t-1), 64u, lane);
                gemm_loop(g_h1 + (size_t)(t-1)*BH + (size_t)b0*Hn, sb, aoff, wboff,
                          W0OFF, accR, 0, 4, mg, nh, lane);
            }

            // freshest dependency LAST: xp partial K 256..511 (+bias1)
            warp_wait(cnt_ptr(2, bt, mg, t), 64u, lane);
            {
                const float* xps = g_xp + ((((size_t)t*2 + bt)*32 + nt)*256 + tid)*32;
                #pragma unroll
                for (int i = 0; i < 8; ++i){
                    float4 v = *(const float4*)(xps + i*4);
                    accR[i*4+0] += v.x; accR[i*4+1] += v.y;
                    accR[i*4+2] += v.z; accR[i*4+3] += v.w;
                }
            }

            #pragma unroll
            for (int mh = 0; mh < 2; ++mh)
                #pragma unroll
                for (int rs = 0; rs < 2; ++rs){
                    int row = rb0 + mh*16 + rs*8;
                    float hv[2];
                    #pragma unroll
                    for (int j = 0; j < 2; ++j){
                        float ai = accR[(mh*4+0)*4 + rs*2 + j];
                        float af = accR[(mh*4+1)*4 + rs*2 + j];
                        float ag = accR[(mh*4+2)*4 + rs*2 + j];
                        float ao = accR[(mh*4+3)*4 + rs*2 + j];
                        int ci = mh*4 + rs*2 + j;
                        c[ci] = fsig(af) * c[ci] + fsig(ai) * ftanh(ag);
                        hv[j] = fsig(ao) * ftanh(c[ci]);
                    }
                    size_t ob = (size_t)t*BH + (size_t)(b0+row)*Hn + ubase;
                    *(uint32_t*)(g_h1 + ob) = packh2(hv[0], hv[1]);
                }

            warp_publish(cnt_ptr(1, bt, mg, t), lane);
        }
    }
}

// ---------------- heads ----------------
__global__ void __launch_bounds__(256) heads_kernel(
    const float* __restrict__ x_stat,
    const float* __restrict__ fc1_w, const float* __restrict__ fc1_b,
    const float* __restrict__ fc2_w, const float* __restrict__ fc2_b,
    const float* __restrict__ fc3_w, const float* __restrict__ fc3_b,
    float* __restrict__ out)
{
    const int b = blockIdx.x;
    const int tid = threadIdx.x;

    float p0 = 0.f, p1 = 0.f;
    for (int idx = tid; idx < Tn*Hn; idx += 256){
        int t = idx >> 9;
        int u = idx & 511;
        float hv = __half2float(g_h1[(size_t)t * BH + (size_t)b * Hn + u]);
        p0 += hv * fc1_w[idx];
        p1 += hv * fc1_w[Tn*Hn + idx];
    }
    __shared__ float s0[256], s1[256];
    s0[tid] = p0; s1[tid] = p1;
    __syncthreads();
    for (int s = 128; s > 0; s >>= 1){
        if (tid < s){ s0[tid] += s0[tid+s]; s1[tid] += s1[tid+s]; }
        __syncthreads();
    }
    if (tid == 0){
        float tp0 = s0[0] + fc1_b[0];
        float tp1 = s1[0] + fc1_b[1];
        float xs0 = x_stat[b*3+0], xs1 = x_stat[b*3+1], xs2 = x_stat[b*3+2];
        float sp0 = fc2_b[0] + xs0*fc2_w[0] + xs1*fc2_w[1] + xs2*fc2_w[2];
        float sp1 = fc2_b[1] + xs0*fc2_w[3] + xs1*fc2_w[4] + xs2*fc2_w[5];
        out[b*2+0] = fc3_b[0] + fc3_w[0]*sp0 + fc3_w[1]*sp1 + fc3_w[2]*tp0 + fc3_w[3]*tp1;
        out[b*2+1] = fc3_b[1] + fc3_w[4]*sp0 + fc3_w[5]*sp1 + fc3_w[6]*tp0 + fc3_w[7]*tp1;
    }
}

extern "C" void kernel_launch(void* const* d_in, const int* in_sizes, int n_in,
                              void* d_out, int out_size)
{
    const float* x_time = (const float*)d_in[0];
    const float* x_stat = (const float*)d_in[1];
    const float* w_ih0  = (const float*)d_in[2];
    const float* w_hh0  = (const float*)d_in[3];
    const float* b0     = (const float*)d_in[4];
    const float* w_ih1  = (const float*)d_in[5];
    const float* w_hh1  = (const float*)d_in[6];
    const float* b1     = (const float*)d_in[7];
    const float* fc1_w  = (const float*)d_in[8];
    const float* fc1_b  = (const float*)d_in[9];
    const float* fc2_w  = (const float*)d_in[10];
    const float* fc2_b  = (const float*)d_in[11];
    const float* fc3_w  = (const float*)d_in[12];
    const float* fc3_b  = (const float*)d_in[13];
    float* out = (float*)d_out;

    cudaFuncSetAttribute(lstm_fused, cudaFuncAttributeMaxDynamicSharedMemorySize, SMEMSZ);

    conv_all_kernel<<<(G4*Hn + 255)/256, 256>>>(w_hh0, w_hh1, w_ih1);
    lstm_fused<<<128, 256, SMEMSZ>>>(x_time, w_ih0, b0, b1);
    heads_kernel<<<Bn, 256>>>(x_stat, fc1_w, fc1_b, fc2_w, fc2_b, fc3_w, fc3_b, out);
}

// round 15
// speedup vs baseline: 1.3107x; 1.2374x over previous
#include <cuda_runtime.h>
#include <cuda_fp16.h>
#include <cstdint>
#include <math.h>

#define Tn 256
#define Bn 256
#define Hn 512
#define BH (Bn*Hn)
#define G4 2048

// ---------------- device globals (scratch) ----------------
__device__ __align__(128) __half g_whh0[G4*Hn];
__device__ __align__(128) __half g_whh1[G4*Hn];
__device__ __align__(128) __half g_wih1[G4*Hn];
// h in MMA A-fragment layout: [t][bt][rt(8)][k16(32)][lane(32)] uint4 = {a0,a1,a2,a3}
__device__ __align__(128) uint4 g_h0f[(size_t)Tn*2*8*1024];
__device__ __align__(128) uint4 g_h1f[(size_t)Tn*2*8*1024];
__device__ __align__(128) __half g_h1[(size_t)Tn*BH];      // linear copy for heads
__device__ __align__(128) float g_xp[134217728];           // [t][bt][nt][tid(256)][32]
__device__ __align__(128) unsigned g_cnt[16*257*8];        // (k,bt,mg,t) counters

// ---------------- SMEM layout (bytes): W tiles only ----------------
#define W0OFF 0
#define W1OFF 66560
#define WIH0OFF 133120
#define SMEMSZ 135168

// ---------------- PTX helpers ----------------
__device__ __forceinline__ uint32_t su32(const void* p){
    uint32_t a;
    asm("{ .reg .u64 t; cvta.to.shared.u64 t, %1; cvt.u32.u64 %0, t; }" : "=r"(a) : "l"(p));
    return a;
}
__device__ __forceinline__ void ldmx4(uint32_t* r, uint32_t a){
    asm volatile("ldmatrix.sync.aligned.m8n8.x4.shared.b16 {%0,%1,%2,%3}, [%4];"
        : "=r"(r[0]), "=r"(r[1]), "=r"(r[2]), "=r"(r[3]) : "r"(a));
}
__device__ __forceinline__ void mma_f16(float* c, const uint32_t* a, uint32_t b0, uint32_t b1){
    asm("mma.sync.aligned.m16n8k16.row.col.f32.f16.f16.f32 "
        "{%0,%1,%2,%3}, {%4,%5,%6,%7}, {%8,%9}, {%0,%1,%2,%3};"
        : "+f"(c[0]), "+f"(c[1]), "+f"(c[2]), "+f"(c[3])
        : "r"(a[0]), "r"(a[1]), "r"(a[2]), "r"(a[3]), "r"(b0), "r"(b1));
}
__device__ __forceinline__ uint32_t packh2(float a, float b){
    __half2 v = __floats2half2_rn(a, b);
    return *(uint32_t*)&v;
}
__device__ __forceinline__ float fsig(float x){
    return __fdividef(1.f, 1.f + __expf(-x));
}
__device__ __forceinline__ float ftanh(float x){
    return 1.f - __fdividef(2.f, __expf(2.f*x) + 1.f);
}

// ---------------- per-warp counter sync ----------------
__device__ __forceinline__ unsigned* cnt_ptr(int k, int bt, int mg, int t){
    return &g_cnt[(size_t)(((k*2 + bt)*4 + mg)*257 + t)*8];
}
__device__ __forceinline__ void warp_wait(unsigned* p, unsigned tgt, int lane){
    if (lane == 0){
        volatile unsigned* v = p;
        while (*v < tgt) {}
        __threadfence();
    }
    __syncwarp();
}
__device__ __forceinline__ void warp_publish(unsigned* p, int lane){
    __threadfence();
    __syncwarp();
    if (lane == 0) atomicAdd(p, 1u);
}

// ---------------- prologue ----------------
__global__ void conv_all_kernel(const float* __restrict__ whh0,
                                const float* __restrict__ whh1,
                                const float* __restrict__ wih1)
{
    int i = blockIdx.x * blockDim.x + threadIdx.x;
    if (i < 16*257*8) g_cnt[i] = 0u;
    if (i >= G4*Hn) return;
    g_whh0[i] = __float2half_rn(whh0[i]);
    g_whh1[i] = __float2half_rn(whh1[i]);
    g_wih1[i] = __float2half_rn(wih1[i]);
}

// ---------------- persistent W tile ----------------
__device__ __forceinline__ void stage_W(const __half* __restrict__ src,
                                        char* smem, int woff, int u0, int tid)
{
    for (int it = 0; it < 16; ++it){
        int idx = tid + it*256;
        int row = idx >> 6;
        int kk  = (idx & 63) << 3;
        int j = ((row >> 3) & 3) * Hn + u0 + (row & 7) + (row >> 5) * 8;
        uint4 v = *(const uint4*)(src + (size_t)j * Hn + kk);
        *(uint4*)(smem + woff + row*1040 + kk*2) = v;
    }
}

// ---------------- fragment GEMM: A from global fragments, W from smem ----------------
// NK k16 steps; for k < XPK also accumulate accX against wx (role-0 fused xp).
// A prefetch depth 4 (covers L2 latency), W (smem) depth 2.
template<int NK, int XPK>
__device__ __forceinline__ void frag_gemm(const uint4* __restrict__ Fm0,
                                          const uint4* __restrict__ Fm1,
                                          uint32_t wrB, uint32_t wxB,
                                          float* accR, float* accX, int lane)
{
    uint4 fa[4][2];
    uint32_t wr[2][8], wx[2][8];
    #pragma unroll
    for (int p = 0; p < 4 && p < NK; ++p){
        fa[p][0] = Fm0[p*32 + lane];
        fa[p][1] = Fm1[p*32 + lane];
    }
    ldmx4(wr[0],     wrB);
    ldmx4(wr[0] + 4, wrB + 16640);
    if (XPK > 0){ ldmx4(wx[0], wxB); ldmx4(wx[0] + 4, wxB + 16640); }
    #pragma unroll
    for (int k = 0; k < NK; ++k){
        const int cur = k & 3;
        const int wc  = k & 1;
        const int wn  = 1 - wc;
        uint4 A0 = fa[cur][0];
        uint4 A1 = fa[cur][1];
        if (k + 4 < NK){
            fa[cur][0] = Fm0[(k+4)*32 + lane];
            fa[cur][1] = Fm1[(k+4)*32 + lane];
        }
        if (k + 1 < NK){
            ldmx4(wr[wn],     wrB + (k+1)*32);
            ldmx4(wr[wn] + 4, wrB + 16640 + (k+1)*32);
            if (XPK > 0 && (k+1) < XPK){
                ldmx4(wx[wn],     wxB + (k+1)*32);
                ldmx4(wx[wn] + 4, wxB + 16640 + (k+1)*32);
            }
        }
        const uint32_t* a0 = (const uint32_t*)&A0;
        const uint32_t* a1 = (const uint32_t*)&A1;
        #pragma unroll
        for (int g = 0; g < 4; ++g){
            mma_f16(accR + (0*4+g)*4, a0, wr[wc][g*2], wr[wc][g*2+1]);
            mma_f16(accR + (1*4+g)*4, a1, wr[wc][g*2], wr[wc][g*2+1]);
        }
        if (XPK > 0 && k < XPK){
            #pragma unroll
            for (int g = 0; g < 4; ++g){
                mma_f16(accX + (0*4+g)*4, a0, wx[wc][g*2], wx[wc][g*2+1]);
                mma_f16(accX + (1*4+g)*4, a1, wx[wc][g*2], wx[wc][g*2+1]);
            }
        }
    }
}

// fragment tile pointer: [t][bt][rt] base
__device__ __forceinline__ const uint4* ftile(const uint4* base, int t, int bt, int rt){
    return base + (((size_t)t*2 + bt)*8 + rt)*1024;
}

// ---------------- fused two-layer pipelined kernel ----------------
// 128 CTAs: role 0 = layer0 rec + xp K 0..255 (fused, shares A frags);
//           role 1 = layer1 rec + xp K 256..511.
// Per role: 2 bt (128 b) x 32 nt (16 u). 8 warps: mg = wid>>1 (m32), nh = wid&1 (n32).
__global__ void __launch_bounds__(256, 1) lstm_fused(
    const float* __restrict__ x_time, const float* __restrict__ w_ih0,
    const float* __restrict__ bias0, const float* __restrict__ bias1)
{
    extern __shared__ __align__(128) char smem[];
    const int tid  = threadIdx.x;
    const int lane = tid & 31;
    const int wid  = tid >> 5;
    const int mg   = wid >> 1;
    const int nh   = wid & 1;
    const int role = blockIdx.x >> 6;
    const int lidx = blockIdx.x & 63;
    const int bt   = lidx >> 5;
    const int nt   = lidx & 31;
    const int b0   = bt * 128;
    const int u0   = nt * 16;
    const uint32_t sb = su32(smem);

    const uint32_t wboff = (uint32_t)((nh*32 + (lane & 7) + ((lane >> 4) & 1) * 8) * 1040
                                      + ((lane >> 3) & 1) * 16);
    const int q2    = 2 * (lane & 3);
    const int rb0   = mg*32 + (lane >> 2);
    const int ubase = u0 + nh*8 + q2;

    if (role == 0){
        // ================= layer 0 rec + fused xp K 0..255 =================
        stage_W(g_whh0, smem, W0OFF, u0, tid);
        stage_W(g_wih1, smem, W1OFF, u0, tid);
        float* s_wih0 = (float*)(smem + WIH0OFF);
        if (tid < 64){
            int j = ((tid >> 3) & 3) * Hn + u0 + (tid & 7) + (tid >> 5) * 8;
            #pragma unroll
            for (int q = 0; q < 5; ++q) s_wih0[tid*5 + q] = w_ih0[(size_t)j*5 + q];
        }
        float breg[4][2], bx[4][2];
        #pragma unroll
        for (int g = 0; g < 4; ++g){
            breg[g][0] = bias0[g*Hn + ubase];
            breg[g][1] = bias0[g*Hn + ubase + 1];
            bx[g][0]   = bias1[g*Hn + ubase];
            bx[g][1]   = bias1[g*Hn + ubase + 1];
        }
        __syncthreads();

        float c[8];
        #pragma unroll
        for (int i = 0; i < 8; ++i) c[i] = 0.f;

        for (int t = 0; t <= Tn; ++t){
            float xr[4][5];
            if (t < Tn){
                #pragma unroll
                for (int mh = 0; mh < 2; ++mh)
                    #pragma unroll
                    for (int rs = 0; rs < 2; ++rs){
                        const float* p = x_time
                            + ((size_t)(b0 + rb0 + mh*16 + rs*8) * Tn + t) * 5;
                        #pragma unroll
                        for (int q = 0; q < 5; ++q) xr[mh*2+rs][q] = p[q];
                    }
            }

            float accR[32], accX[32];
            #pragma unroll
            for (int i = 0; i < 32; ++i){ accR[i] = 0.f; accX[i] = 0.f; }

            if (t > 0){
                warp_wait(cnt_ptr(0, bt, mg, t-1), 64u, lane);
                const uint4* fb = ftile(g_h0f, t-1, bt, mg*2);
                frag_gemm<32,16>(fb, fb + 1024, sb + W0OFF + wboff, sb + W1OFF + wboff,
                                 accR, accX, lane);
            }

            if (t < Tn){
                #pragma unroll
                for (int mh = 0; mh < 2; ++mh)
                    #pragma unroll
                    for (int rs = 0; rs < 2; ++rs)
                        #pragma unroll
                        for (int g = 0; g < 4; ++g)
                            #pragma unroll
                            for (int j = 0; j < 2; ++j){
                                const float* wr = s_wih0 + (nh*32 + g*8 + q2 + j)*5;
                                float d = breg[g][j];
                                #pragma unroll
                                for (int q = 0; q < 5; ++q) d += xr[mh*2+rs][q]*wr[q];
                                accR[(mh*4+g)*4 + rs*2 + j] += d;
                            }
                // epilogue: write h0_t directly in fragment layout (1 STG.64 per mh)
                #pragma unroll
                for (int mh = 0; mh < 2; ++mh){
                    uint32_t w[2];
                    #pragma unroll
                    for (int rs = 0; rs < 2; ++rs){
                        float hv[2];
                        #pragma unroll
                        for (int j = 0; j < 2; ++j){
                            float ai = accR[(mh*4+0)*4 + rs*2 + j];
                            float af = accR[(mh*4+1)*4 + rs*2 + j];
                            float ag = accR[(mh*4+2)*4 + rs*2 + j];
                            float ao = accR[(mh*4+3)*4 + rs*2 + j];
                            int ci = mh*4 + rs*2 + j;
                            c[ci] = fsig(af) * c[ci] + fsig(ai) * ftanh(ag);
                            hv[j] = fsig(ao) * ftanh(c[ci]);
                        }
                        w[rs] = packh2(hv[0], hv[1]);
                    }
                    uint4* fp = g_h0f + (((size_t)t*2 + bt)*8 + mg*2 + mh)*1024
                              + nt*32 + lane;
                    *(uint2*)((uint32_t*)fp + nh*2) = make_uint2(w[0], w[1]);
                }
            }

            if (t > 0){
                float* xp = g_xp + ((((size_t)(t-1)*2 + bt)*32 + nt)*256 + tid)*32;
                #pragma unroll
                for (int mh = 0; mh < 2; ++mh)
                    #pragma unroll
                    for (int g = 0; g < 4; ++g){
                        int i = mh*4 + g;
                        float4 v;
                        v.x = accX[i*4+0] + bx[g][0];
                        v.y = accX[i*4+1] + bx[g][1];
                        v.z = accX[i*4+2] + bx[g][0];
                        v.w = accX[i*4+3] + bx[g][1];
                        *(float4*)(xp + i*4) = v;
                    }
            }

            warp_publish(cnt_ptr(0, bt, mg, t), lane);
        }
    } else {
        // ================= layer 1 rec + xp K 256..511 =================
        stage_W(g_whh1, smem, W0OFF, u0, tid);
        stage_W(g_wih1, smem, W1OFF, u0, tid);
        __syncthreads();

        float c[8];
        #pragma unroll
        for (int i = 0; i < 8; ++i) c[i] = 0.f;

        for (int t = 0; t < Tn; ++t){
            // covers h0_t (step t) and xp-partial_t (step t+1)
            warp_wait(cnt_ptr(0, bt, mg, t+1), 64u, lane);

            float accR[32];
            {
                const float* xps = g_xp + ((((size_t)t*2 + bt)*32 + nt)*256 + tid)*32;
                #pragma unroll
                for (int i = 0; i < 8; ++i){
                    float4 v = *(const float4*)(xps + i*4);
                    accR[i*4+0] = v.x; accR[i*4+1] = v.y;
                    accR[i*4+2] = v.z; accR[i*4+3] = v.w;
                }
            }

            // xp K 256..511: h0f[t] k16 16..31 vs wih1
            {
                const uint4* fb = ftile(g_h0f, t, bt, mg*2);
                frag_gemm<16,0>(fb + 16*32, fb + 1024 + 16*32,
                                sb + W1OFF + wboff + 512, 0u, accR, (float*)0, lane);
            }

            if (t > 0){
                warp_wait(cnt_ptr(1, bt, mg, t-1), 64u, lane);
                const uint4* fb = ftile(g_h1f, t-1, bt, mg*2);
                frag_gemm<32,0>(fb, fb + 1024, sb + W0OFF + wboff, 0u,
                                accR, (float*)0, lane);
            }

            // epilogue: h1 fragment layout + linear copy for heads
            #pragma unroll
            for (int mh = 0; mh < 2; ++mh){
                uint32_t w[2];
                #pragma unroll
                for (int rs = 0; rs < 2; ++rs){
                    float hv[2];
                    #pragma unroll
                    for (int j = 0; j < 2; ++j){
                        float ai = accR[(mh*4+0)*4 + rs*2 + j];
                        float af = accR[(mh*4+1)*4 + rs*2 + j];
                        float ag = accR[(mh*4+2)*4 + rs*2 + j];
                        float ao = accR[(mh*4+3)*4 + rs*2 + j];
                        int ci = mh*4 + rs*2 + j;
                        c[ci] = fsig(af) * c[ci] + fsig(ai) * ftanh(ag);
                        hv[j] = fsig(ao) * ftanh(c[ci]);
                    }
                    w[rs] = packh2(hv[0], hv[1]);
                    int row = rb0 + mh*16 + rs*8;
                    *(uint32_t*)(g_h1 + (size_t)t*BH + (size_t)(b0+row)*Hn + ubase) = w[rs];
                }
                uint4* fp = g_h1f + (((size_t)t*2 + bt)*8 + mg*2 + mh)*1024
                          + nt*32 + lane;
                *(uint2*)((uint32_t*)fp + nh*2) = make_uint2(w[0], w[1]);
            }

            warp_publish(cnt_ptr(1, bt, mg, t), lane);
        }
    }
}

// ---------------- heads ----------------
__global__ void __launch_bounds__(256) heads_kernel(
    const float* __restrict__ x_stat,
    const float* __restrict__ fc1_w, const float* __restrict__ fc1_b,
    const float* __restrict__ fc2_w, const float* __restrict__ fc2_b,
    const float* __restrict__ fc3_w, const float* __restrict__ fc3_b,
    float* __restrict__ out)
{
    const int b = blockIdx.x;
    const int tid = threadIdx.x;

    float p0 = 0.f, p1 = 0.f;
    for (int idx = tid; idx < Tn*Hn; idx += 256){
        int t = idx >> 9;
        int u = idx & 511;
        float hv = __half2float(g_h1[(size_t)t * BH + (size_t)b * Hn + u]);
        p0 += hv * fc1_w[idx];
        p1 += hv * fc1_w[Tn*Hn + idx];
    }
    __shared__ float s0[256], s1[256];
    s0[tid] = p0; s1[tid] = p1;
    __syncthreads();
    for (int s = 128; s > 0; s >>= 1){
        if (tid < s){ s0[tid] += s0[tid+s]; s1[tid] += s1[tid+s]; }
        __syncthreads();
    }
    if (tid == 0){
        float tp0 = s0[0] + fc1_b[0];
        float tp1 = s1[0] + fc1_b[1];
        float xs0 = x_stat[b*3+0], xs1 = x_stat[b*3+1], xs2 = x_stat[b*3+2];
        float sp0 = fc2_b[0] + xs0*fc2_w[0] + xs1*fc2_w[1] + xs2*fc2_w[2];
        float sp1 = fc2_b[1] + xs0*fc2_w[3] + xs1*fc2_w[4] + xs2*fc2_w[5];
        out[b*2+0] = fc3_b[0] + fc3_w[0]*sp0 + fc3_w[1]*sp1 + fc3_w[2]*tp0 + fc3_w[3]*tp1;
        out[b*2+1] = fc3_b[1] + fc3_w[4]*sp0 + fc3_w[5]*sp1 + fc3_w[6]*tp0 + fc3_w[7]*tp1;
    }
}

extern "C" void kernel_launch(void* const* d_in, const int* in_sizes, int n_in,
                              void* d_out, int out_size)
{
    const float* x_time = (const float*)d_in[0];
    const float* x_stat = (const float*)d_in[1];
    const float* w_ih0  = (const float*)d_in[2];
    const float* w_hh0  = (const float*)d_in[3];
    const float* b0     = (const float*)d_in[4];
    const float* w_ih1  = (const float*)d_in[5];
    const float* w_hh1  = (const float*)d_in[6];
    const float* b1     = (const float*)d_in[7];
    const float* fc1_w  = (const float*)d_in[8];
    const float* fc1_b  = (const float*)d_in[9];
    const float* fc2_w  = (const float*)d_in[10];
    const float* fc2_b  = (const float*)d_in[11];
    const float* fc3_w  = (const float*)d_in[12];
    const float* fc3_b  = (const float*)d_in[13];
    float* out = (float*)d_out;

    cudaFuncSetAttribute(lstm_fused, cudaFuncAttributeMaxDynamicSharedMemorySize, SMEMSZ);

    conv_all_kernel<<<(G4*Hn + 255)/256, 256>>>(w_hh0, w_hh1, w_ih1);
    lstm_fused<<<128, 256, SMEMSZ>>>(x_time, w_ih0, b0, b1);
    heads_kernel<<<Bn, 256>>>(x_stat, fc1_w, fc1_b, fc2_w, fc2_b, fc3_w, fc3_b, out);
}